// round 6
// baseline (speedup 1.0000x reference)
#include <cuda_runtime.h>

#define KDIM     40960
#define BROWS    8192
#define MDIM     4
#define K_TILE   2048                 // 4 x 2048 x 4B = 32 KB smem per block
#define NCHUNK   (KDIM / K_TILE)     // 20
#define ROWS_PB  8                   // 8 rows per block (one warp each)
#define GRIDX    (BROWS / ROWS_PB)   // 1024  -> 1024 x 20 = 20480 blocks
#define THREADS  256

// Partial FT sums: [chunk][row][8] (aw0..3, ab0..3). Each slot written exactly
// once per launch -> no zeroing, no atomics, deterministic.
__device__ float g_partial[(size_t)NCHUNK * BROWS * 8];

__global__ __launch_bounds__(THREADS, 5) void nnue_ft_kernel(
    const float* __restrict__ wfeat,   // (B, K)
    const float* __restrict__ bfeat,   // (B, K)
    const float* __restrict__ ft_w)    // (M, K)
{
    __shared__ float wsm[MDIM][K_TILE];

    const int chunk = blockIdx.y;
    const int kbase = chunk * K_TILE;

    // Stage this chunk's weights (L2-resident; 640 KB total working set).
    #pragma unroll
    for (int i = threadIdx.x; i < MDIM * (K_TILE / 4); i += THREADS) {
        const int m  = i / (K_TILE / 4);
        const int kk = i % (K_TILE / 4);
        ((float4*)wsm[m])[kk] =
            ((const float4*)(ft_w + (size_t)m * KDIM + kbase))[kk];
    }
    __syncthreads();

    const int warp = threadIdx.x >> 5;
    const int lane = threadIdx.x & 31;
    const int row  = blockIdx.x * ROWS_PB + warp;

    const float4* __restrict__ wrow =
        (const float4*)(wfeat + (size_t)row * KDIM + kbase);
    const float4* __restrict__ brow =
        (const float4*)(bfeat + (size_t)row * KDIM + kbase);

    float aw0 = 0.f, aw1 = 0.f, aw2 = 0.f, aw3 = 0.f;
    float ab0 = 0.f, ab1 = 0.f, ab2 = 0.f, ab3 = 0.f;

    #pragma unroll 4
    for (int j = 0; j < K_TILE / 4 / 32; ++j) {   // 16 iterations
        const int i = lane + 32 * j;
        const float4 wv = __ldcs(wrow + i);   // streaming: zero reuse
        const float4 bv = __ldcs(brow + i);
        const float4 m0 = ((const float4*)wsm[0])[i];
        const float4 m1 = ((const float4*)wsm[1])[i];
        const float4 m2 = ((const float4*)wsm[2])[i];
        const float4 m3 = ((const float4*)wsm[3])[i];

        aw0 += wv.x*m0.x + wv.y*m0.y + wv.z*m0.z + wv.w*m0.w;
        aw1 += wv.x*m1.x + wv.y*m1.y + wv.z*m1.z + wv.w*m1.w;
        aw2 += wv.x*m2.x + wv.y*m2.y + wv.z*m2.z + wv.w*m2.w;
        aw3 += wv.x*m3.x + wv.y*m3.y + wv.z*m3.z + wv.w*m3.w;

        ab0 += bv.x*m0.x + bv.y*m0.y + bv.z*m0.z + bv.w*m0.w;
        ab1 += bv.x*m1.x + bv.y*m1.y + bv.z*m1.z + bv.w*m1.w;
        ab2 += bv.x*m2.x + bv.y*m2.y + bv.z*m2.z + bv.w*m2.w;
        ab3 += bv.x*m3.x + bv.y*m3.y + bv.z*m3.z + bv.w*m3.w;
    }

    #pragma unroll
    for (int off = 16; off > 0; off >>= 1) {
        aw0 += __shfl_xor_sync(0xFFFFFFFFu, aw0, off);
        aw1 += __shfl_xor_sync(0xFFFFFFFFu, aw1, off);
        aw2 += __shfl_xor_sync(0xFFFFFFFFu, aw2, off);
        aw3 += __shfl_xor_sync(0xFFFFFFFFu, aw3, off);
        ab0 += __shfl_xor_sync(0xFFFFFFFFu, ab0, off);
        ab1 += __shfl_xor_sync(0xFFFFFFFFu, ab1, off);
        ab2 += __shfl_xor_sync(0xFFFFFFFFu, ab2, off);
        ab3 += __shfl_xor_sync(0xFFFFFFFFu, ab3, off);
    }

    if (lane == 0) {
        float4* dst = (float4*)&g_partial[((size_t)chunk * BROWS + row) * 8];
        dst[0] = make_float4(aw0, aw1, aw2, aw3);
        dst[1] = make_float4(ab0, ab1, ab2, ab3);
    }
}

// Head: 4 workers per row, each reduces 5 chunks; smem combine; worker 0 runs MLP.
#define HEAD_THREADS 256
#define WORKERS      4
#define ROWS_PER_HB  (HEAD_THREADS / WORKERS)   // 64 rows per block
#define CHUNKS_PW    (NCHUNK / WORKERS)         // 5

__global__ __launch_bounds__(HEAD_THREADS) void nnue_head_kernel(
    const float* __restrict__ stm,
    const float* __restrict__ ft_b,
    const float* __restrict__ l1_w,
    const float* __restrict__ l1_b,
    const float* __restrict__ l2_w,
    const float* __restrict__ l2_b,
    float* __restrict__ out)
{
    __shared__ float red[WORKERS][ROWS_PER_HB][8];

    const int rloc   = threadIdx.x & (ROWS_PER_HB - 1);   // 0..63
    const int worker = threadIdx.x >> 6;                  // 0..3
    const int row    = blockIdx.x * ROWS_PER_HB + rloc;

    float aw0 = 0.f, aw1 = 0.f, aw2 = 0.f, aw3 = 0.f;
    float ab0 = 0.f, ab1 = 0.f, ab2 = 0.f, ab3 = 0.f;

    #pragma unroll
    for (int cc = 0; cc < CHUNKS_PW; ++cc) {
        const int c = worker * CHUNKS_PW + cc;
        const float4* p = (const float4*)&g_partial[((size_t)c * BROWS + row) * 8];
        const float4 a = p[0];
        const float4 b = p[1];
        aw0 += a.x; aw1 += a.y; aw2 += a.z; aw3 += a.w;
        ab0 += b.x; ab1 += b.y; ab2 += b.z; ab3 += b.w;
    }

    ((float4*)red[worker][rloc])[0] = make_float4(aw0, aw1, aw2, aw3);
    ((float4*)red[worker][rloc])[1] = make_float4(ab0, ab1, ab2, ab3);
    __syncthreads();

    if (worker == 0) {
        #pragma unroll
        for (int wk = 1; wk < WORKERS; ++wk) {
            const float4 a = ((const float4*)red[wk][rloc])[0];
            const float4 b = ((const float4*)red[wk][rloc])[1];
            aw0 += a.x; aw1 += a.y; aw2 += a.z; aw3 += a.w;
            ab0 += b.x; ab1 += b.y; ab2 += b.z; ab3 += b.w;
        }

        float w[4], b[4];
        w[0] = aw0 + ft_b[0]; w[1] = aw1 + ft_b[1];
        w[2] = aw2 + ft_b[2]; w[3] = aw3 + ft_b[3];
        b[0] = ab0 + ft_b[0]; b[1] = ab1 + ft_b[1];
        b[2] = ab2 + ft_b[2]; b[3] = ab3 + ft_b[3];

        const float s  = stm[row];
        const float os = 1.0f - s;

        float x[8];
        #pragma unroll
        for (int m = 0; m < 4; ++m) {
            x[m]     = fminf(fmaxf(s * w[m] + os * b[m], 0.f), 1.f);
            x[m + 4] = fminf(fmaxf(s * b[m] + os * w[m], 0.f), 1.f);
        }

        float res = l2_b[0];
        #pragma unroll
        for (int n = 0; n < 8; ++n) {
            float y = l1_b[n];
            #pragma unroll
            for (int j = 0; j < 8; ++j)
                y += l1_w[n * 8 + j] * x[j];
            y = fminf(fmaxf(y, 0.f), 1.f);
            res += l2_w[n] * y;
        }
        out[row] = res;
    }
}

extern "C" void kernel_launch(void* const* d_in, const int* in_sizes, int n_in,
                              void* d_out, int out_size) {
    const float* wfeat = (const float*)d_in[0];
    const float* bfeat = (const float*)d_in[1];
    const float* stm   = (const float*)d_in[2];
    const float* ft_w  = (const float*)d_in[3];
    const float* ft_b  = (const float*)d_in[4];
    const float* l1_w  = (const float*)d_in[5];
    const float* l1_b  = (const float*)d_in[6];
    const float* l2_w  = (const float*)d_in[7];
    const float* l2_b  = (const float*)d_in[8];
    float* out = (float*)d_out;

    dim3 grid1(GRIDX, NCHUNK);
    nnue_ft_kernel<<<grid1, THREADS>>>(wfeat, bfeat, ft_w);
    nnue_head_kernel<<<BROWS / ROWS_PER_HB, HEAD_THREADS>>>(
        stm, ft_b, l1_w, l1_b, l2_w, l2_b, out);
}

// round 8
// speedup vs baseline: 1.2166x; 1.2166x over previous
#include <cuda_runtime.h>

#define KDIM     40960
#define BROWS    8192
#define MDIM     4
#define K_TILE   2048                 // 4 x 2048 x 4B = 32 KB smem per block
#define NCHUNK   (KDIM / K_TILE)     // 20
#define ROWS_PB  8                   // 8 rows per block (one warp each)
#define GRIDX    (BROWS / ROWS_PB)   // 1024  -> 1024 x 20 = 20480 blocks
#define THREADS  256

// Partial FT sums: [chunk][row][8] (aw0..3, ab0..3). Each slot written exactly
// once per launch -> no zeroing, no atomics, deterministic.
__device__ float g_partial[(size_t)NCHUNK * BROWS * 8];

// FT kernel: identical to the R3 known-good version (57 regs, 4 blocks/SM,
// default cache policy). No launch_bounds occupancy cap (spills), no __ldcs.
__global__ __launch_bounds__(THREADS) void nnue_ft_kernel(
    const float* __restrict__ wfeat,   // (B, K)
    const float* __restrict__ bfeat,   // (B, K)
    const float* __restrict__ ft_w)    // (M, K)
{
    __shared__ float wsm[MDIM][K_TILE];

    const int chunk = blockIdx.y;
    const int kbase = chunk * K_TILE;

    // Stage this chunk's weights (L2-resident; 640 KB total working set).
    #pragma unroll
    for (int i = threadIdx.x; i < MDIM * (K_TILE / 4); i += THREADS) {
        const int m  = i / (K_TILE / 4);
        const int kk = i % (K_TILE / 4);
        ((float4*)wsm[m])[kk] =
            ((const float4*)(ft_w + (size_t)m * KDIM + kbase))[kk];
    }
    __syncthreads();

    const int warp = threadIdx.x >> 5;
    const int lane = threadIdx.x & 31;
    const int row  = blockIdx.x * ROWS_PB + warp;

    const float4* __restrict__ wrow =
        (const float4*)(wfeat + (size_t)row * KDIM + kbase);
    const float4* __restrict__ brow =
        (const float4*)(bfeat + (size_t)row * KDIM + kbase);

    float aw0 = 0.f, aw1 = 0.f, aw2 = 0.f, aw3 = 0.f;
    float ab0 = 0.f, ab1 = 0.f, ab2 = 0.f, ab3 = 0.f;

    #pragma unroll 4
    for (int j = 0; j < K_TILE / 4 / 32; ++j) {   // 16 iterations
        const int i = lane + 32 * j;
        const float4 wv = wrow[i];
        const float4 bv = brow[i];
        const float4 m0 = ((const float4*)wsm[0])[i];
        const float4 m1 = ((const float4*)wsm[1])[i];
        const float4 m2 = ((const float4*)wsm[2])[i];
        const float4 m3 = ((const float4*)wsm[3])[i];

        aw0 += wv.x*m0.x + wv.y*m0.y + wv.z*m0.z + wv.w*m0.w;
        aw1 += wv.x*m1.x + wv.y*m1.y + wv.z*m1.z + wv.w*m1.w;
        aw2 += wv.x*m2.x + wv.y*m2.y + wv.z*m2.z + wv.w*m2.w;
        aw3 += wv.x*m3.x + wv.y*m3.y + wv.z*m3.z + wv.w*m3.w;

        ab0 += bv.x*m0.x + bv.y*m0.y + bv.z*m0.z + bv.w*m0.w;
        ab1 += bv.x*m1.x + bv.y*m1.y + bv.z*m1.z + bv.w*m1.w;
        ab2 += bv.x*m2.x + bv.y*m2.y + bv.z*m2.z + bv.w*m2.w;
        ab3 += bv.x*m3.x + bv.y*m3.y + bv.z*m3.z + bv.w*m3.w;
    }

    #pragma unroll
    for (int off = 16; off > 0; off >>= 1) {
        aw0 += __shfl_xor_sync(0xFFFFFFFFu, aw0, off);
        aw1 += __shfl_xor_sync(0xFFFFFFFFu, aw1, off);
        aw2 += __shfl_xor_sync(0xFFFFFFFFu, aw2, off);
        aw3 += __shfl_xor_sync(0xFFFFFFFFu, aw3, off);
        ab0 += __shfl_xor_sync(0xFFFFFFFFu, ab0, off);
        ab1 += __shfl_xor_sync(0xFFFFFFFFu, ab1, off);
        ab2 += __shfl_xor_sync(0xFFFFFFFFu, ab2, off);
        ab3 += __shfl_xor_sync(0xFFFFFFFFu, ab3, off);
    }

    if (lane == 0) {
        float4* dst = (float4*)&g_partial[((size_t)chunk * BROWS + row) * 8];
        dst[0] = make_float4(aw0, aw1, aw2, aw3);
        dst[1] = make_float4(ab0, ab1, ab2, ab3);
    }
}

// Head: 4 workers per row, each reduces 5 chunks; smem combine; worker 0 runs
// the MLP. (Measured win in R6: 10.6 -> 8.5 us.)
#define HEAD_THREADS 256
#define WORKERS      4
#define ROWS_PER_HB  (HEAD_THREADS / WORKERS)   // 64 rows per block
#define CHUNKS_PW    (NCHUNK / WORKERS)         // 5

__global__ __launch_bounds__(HEAD_THREADS) void nnue_head_kernel(
    const float* __restrict__ stm,
    const float* __restrict__ ft_b,
    const float* __restrict__ l1_w,
    const float* __restrict__ l1_b,
    const float* __restrict__ l2_w,
    const float* __restrict__ l2_b,
    float* __restrict__ out)
{
    __shared__ float red[WORKERS][ROWS_PER_HB][8];

    const int rloc   = threadIdx.x & (ROWS_PER_HB - 1);   // 0..63
    const int worker = threadIdx.x >> 6;                  // 0..3
    const int row    = blockIdx.x * ROWS_PER_HB + rloc;

    float aw0 = 0.f, aw1 = 0.f, aw2 = 0.f, aw3 = 0.f;
    float ab0 = 0.f, ab1 = 0.f, ab2 = 0.f, ab3 = 0.f;

    #pragma unroll
    for (int cc = 0; cc < CHUNKS_PW; ++cc) {
        const int c = worker * CHUNKS_PW + cc;
        const float4* p = (const float4*)&g_partial[((size_t)c * BROWS + row) * 8];
        const float4 a = p[0];
        const float4 b = p[1];
        aw0 += a.x; aw1 += a.y; aw2 += a.z; aw3 += a.w;
        ab0 += b.x; ab1 += b.y; ab2 += b.z; ab3 += b.w;
    }

    ((float4*)red[worker][rloc])[0] = make_float4(aw0, aw1, aw2, aw3);
    ((float4*)red[worker][rloc])[1] = make_float4(ab0, ab1, ab2, ab3);
    __syncthreads();

    if (worker == 0) {
        #pragma unroll
        for (int wk = 1; wk < WORKERS; ++wk) {
            const float4 a = ((const float4*)red[wk][rloc])[0];
            const float4 b = ((const float4*)red[wk][rloc])[1];
            aw0 += a.x; aw1 += a.y; aw2 += a.z; aw3 += a.w;
            ab0 += b.x; ab1 += b.y; ab2 += b.z; ab3 += b.w;
        }

        float w[4], b[4];
        w[0] = aw0 + ft_b[0]; w[1] = aw1 + ft_b[1];
        w[2] = aw2 + ft_b[2]; w[3] = aw3 + ft_b[3];
        b[0] = ab0 + ft_b[0]; b[1] = ab1 + ft_b[1];
        b[2] = ab2 + ft_b[2]; b[3] = ab3 + ft_b[3];

        const float s  = stm[row];
        const float os = 1.0f - s;

        float x[8];
        #pragma unroll
        for (int m = 0; m < 4; ++m) {
            x[m]     = fminf(fmaxf(s * w[m] + os * b[m], 0.f), 1.f);
            x[m + 4] = fminf(fmaxf(s * b[m] + os * w[m], 0.f), 1.f);
        }

        float res = l2_b[0];
        #pragma unroll
        for (int n = 0; n < 8; ++n) {
            float y = l1_b[n];
            #pragma unroll
            for (int j = 0; j < 8; ++j)
                y += l1_w[n * 8 + j] * x[j];
            y = fminf(fmaxf(y, 0.f), 1.f);
            res += l2_w[n] * y;
        }
        out[row] = res;
    }
}

extern "C" void kernel_launch(void* const* d_in, const int* in_sizes, int n_in,
                              void* d_out, int out_size) {
    const float* wfeat = (const float*)d_in[0];
    const float* bfeat = (const float*)d_in[1];
    const float* stm   = (const float*)d_in[2];
    const float* ft_w  = (const float*)d_in[3];
    const float* ft_b  = (const float*)d_in[4];
    const float* l1_w  = (const float*)d_in[5];
    const float* l1_b  = (const float*)d_in[6];
    const float* l2_w  = (const float*)d_in[7];
    const float* l2_b  = (const float*)d_in[8];
    float* out = (float*)d_out;

    dim3 grid1(GRIDX, NCHUNK);
    nnue_ft_kernel<<<grid1, THREADS>>>(wfeat, bfeat, ft_w);
    nnue_head_kernel<<<BROWS / ROWS_PER_HB, HEAD_THREADS>>>(
        stm, ft_b, l1_w, l1_b, l2_w, l2_b, out);
}

// round 10
// speedup vs baseline: 1.2451x; 1.0234x over previous
#include <cuda_runtime.h>

#define KDIM     40960
#define BROWS    8192
#define MDIM     4
#define K_TILE   2048                 // 4 x 2048 x 4B = 32 KB smem per block
#define NCHUNK   (KDIM / K_TILE)     // 20
#define ROWS_PB  8                   // 8 rows per block (one warp each)
#define GRIDX    (BROWS / ROWS_PB)   // 1024  -> 1024 x 20 = 20480 blocks
#define THREADS  256

// Partial FT sums: [chunk][row][8] (aw0..3, ab0..3). Each slot written exactly
// once per launch -> no zeroing, no atomics on data, deterministic.
__device__ float g_partial[(size_t)NCHUNK * BROWS * 8];

// Arrival counters, one per row-group. Zero-initialized at module load; the
// last-arriving block resets its counter to 0, so every graph replay starts
// from the same state.
__device__ int g_counter[GRIDX];

__global__ __launch_bounds__(THREADS, 4) void nnue_fused_kernel(
    const float* __restrict__ wfeat,   // (B, K)
    const float* __restrict__ bfeat,   // (B, K)
    const float* __restrict__ ft_w,    // (M, K)
    const float* __restrict__ stm,     // (B,)
    const float* __restrict__ ft_b,    // (M,)
    const float* __restrict__ l1_w,    // (8, 8)
    const float* __restrict__ l1_b,    // (8,)
    const float* __restrict__ l2_w,    // (1, 8)
    const float* __restrict__ l2_b,    // (1,)
    float* __restrict__ out)           // (B,)
{
    __shared__ float wsm[MDIM][K_TILE];
    __shared__ int   is_last;

    const int chunk = blockIdx.y;
    const int kbase = chunk * K_TILE;

    // Stage this chunk's weights (L2-resident; 640 KB total working set).
    #pragma unroll
    for (int i = threadIdx.x; i < MDIM * (K_TILE / 4); i += THREADS) {
        const int m  = i / (K_TILE / 4);
        const int kk = i % (K_TILE / 4);
        ((float4*)wsm[m])[kk] =
            ((const float4*)(ft_w + (size_t)m * KDIM + kbase))[kk];
    }
    __syncthreads();

    const int warp = threadIdx.x >> 5;
    const int lane = threadIdx.x & 31;
    const int row  = blockIdx.x * ROWS_PB + warp;

    const float4* __restrict__ wrow =
        (const float4*)(wfeat + (size_t)row * KDIM + kbase);
    const float4* __restrict__ brow =
        (const float4*)(bfeat + (size_t)row * KDIM + kbase);

    float aw0 = 0.f, aw1 = 0.f, aw2 = 0.f, aw3 = 0.f;
    float ab0 = 0.f, ab1 = 0.f, ab2 = 0.f, ab3 = 0.f;

    #pragma unroll 4
    for (int j = 0; j < K_TILE / 4 / 32; ++j) {   // 16 iterations
        const int i = lane + 32 * j;
        const float4 wv = wrow[i];
        const float4 bv = brow[i];
        const float4 m0 = ((const float4*)wsm[0])[i];
        const float4 m1 = ((const float4*)wsm[1])[i];
        const float4 m2 = ((const float4*)wsm[2])[i];
        const float4 m3 = ((const float4*)wsm[3])[i];

        aw0 += wv.x*m0.x + wv.y*m0.y + wv.z*m0.z + wv.w*m0.w;
        aw1 += wv.x*m1.x + wv.y*m1.y + wv.z*m1.z + wv.w*m1.w;
        aw2 += wv.x*m2.x + wv.y*m2.y + wv.z*m2.z + wv.w*m2.w;
        aw3 += wv.x*m3.x + wv.y*m3.y + wv.z*m3.z + wv.w*m3.w;

        ab0 += bv.x*m0.x + bv.y*m0.y + bv.z*m0.z + bv.w*m0.w;
        ab1 += bv.x*m1.x + bv.y*m1.y + bv.z*m1.z + bv.w*m1.w;
        ab2 += bv.x*m2.x + bv.y*m2.y + bv.z*m2.z + bv.w*m2.w;
        ab3 += bv.x*m3.x + bv.y*m3.y + bv.z*m3.z + bv.w*m3.w;
    }

    #pragma unroll
    for (int off = 16; off > 0; off >>= 1) {
        aw0 += __shfl_xor_sync(0xFFFFFFFFu, aw0, off);
        aw1 += __shfl_xor_sync(0xFFFFFFFFu, aw1, off);
        aw2 += __shfl_xor_sync(0xFFFFFFFFu, aw2, off);
        aw3 += __shfl_xor_sync(0xFFFFFFFFu, aw3, off);
        ab0 += __shfl_xor_sync(0xFFFFFFFFu, ab0, off);
        ab1 += __shfl_xor_sync(0xFFFFFFFFu, ab1, off);
        ab2 += __shfl_xor_sync(0xFFFFFFFFu, ab2, off);
        ab3 += __shfl_xor_sync(0xFFFFFFFFu, ab3, off);
    }

    if (lane == 0) {
        float4* dst = (float4*)&g_partial[((size_t)chunk * BROWS + row) * 8];
        dst[0] = make_float4(aw0, aw1, aw2, aw3);
        dst[1] = make_float4(ab0, ab1, ab2, ab3);
    }

    // ---- last-arrival detection for this row-group ----
    __threadfence();   // make this block's partial writes globally visible
    if (threadIdx.x == 0) {
        const int old = atomicAdd(&g_counter[blockIdx.x], 1);
        is_last = (old == NCHUNK - 1);
        if (old == NCHUNK - 1) g_counter[blockIdx.x] = 0;  // re-arm for replay
    }
    __syncthreads();
    if (!is_last) return;

    // ---- head (only the last block per row-group; 8 warps = 8 rows) ----
    // Lanes 0..19 each load one chunk's 8 partials; shfl-reduce (fixed order).
    float hw0 = 0.f, hw1 = 0.f, hw2 = 0.f, hw3 = 0.f;
    float hb0 = 0.f, hb1 = 0.f, hb2 = 0.f, hb3 = 0.f;
    if (lane < NCHUNK) {
        const float4* p =
            (const float4*)&g_partial[((size_t)lane * BROWS + row) * 8];
        const float4 a = __ldcg(p);
        const float4 b = __ldcg(p + 1);
        hw0 = a.x; hw1 = a.y; hw2 = a.z; hw3 = a.w;
        hb0 = b.x; hb1 = b.y; hb2 = b.z; hb3 = b.w;
    }
    #pragma unroll
    for (int off = 16; off > 0; off >>= 1) {
        hw0 += __shfl_xor_sync(0xFFFFFFFFu, hw0, off);
        hw1 += __shfl_xor_sync(0xFFFFFFFFu, hw1, off);
        hw2 += __shfl_xor_sync(0xFFFFFFFFu, hw2, off);
        hw3 += __shfl_xor_sync(0xFFFFFFFFu, hw3, off);
        hb0 += __shfl_xor_sync(0xFFFFFFFFu, hb0, off);
        hb1 += __shfl_xor_sync(0xFFFFFFFFu, hb1, off);
        hb2 += __shfl_xor_sync(0xFFFFFFFFu, hb2, off);
        hb3 += __shfl_xor_sync(0xFFFFFFFFu, hb3, off);
    }

    if (lane == 0) {
        float w[4], b[4];
        w[0] = hw0 + ft_b[0]; w[1] = hw1 + ft_b[1];
        w[2] = hw2 + ft_b[2]; w[3] = hw3 + ft_b[3];
        b[0] = hb0 + ft_b[0]; b[1] = hb1 + ft_b[1];
        b[2] = hb2 + ft_b[2]; b[3] = hb3 + ft_b[3];

        const float s  = stm[row];
        const float os = 1.0f - s;

        float x[8];
        #pragma unroll
        for (int m = 0; m < 4; ++m) {
            x[m]     = fminf(fmaxf(s * w[m] + os * b[m], 0.f), 1.f);
            x[m + 4] = fminf(fmaxf(s * b[m] + os * w[m], 0.f), 1.f);
        }

        float res = l2_b[0];
        #pragma unroll
        for (int n = 0; n < 8; ++n) {
            float y = l1_b[n];
            #pragma unroll
            for (int j = 0; j < 8; ++j)
                y += l1_w[n * 8 + j] * x[j];
            y = fminf(fmaxf(y, 0.f), 1.f);
            res += l2_w[n] * y;
        }
        out[row] = res;
    }
}

extern "C" void kernel_launch(void* const* d_in, const int* in_sizes, int n_in,
                              void* d_out, int out_size) {
    const float* wfeat = (const float*)d_in[0];
    const float* bfeat = (const float*)d_in[1];
    const float* stm   = (const float*)d_in[2];
    const float* ft_w  = (const float*)d_in[3];
    const float* ft_b  = (const float*)d_in[4];
    const float* l1_w  = (const float*)d_in[5];
    const float* l1_b  = (const float*)d_in[6];
    const float* l2_w  = (const float*)d_in[7];
    const float* l2_b  = (const float*)d_in[8];
    float* out = (float*)d_out;

    dim3 grid(GRIDX, NCHUNK);
    nnue_fused_kernel<<<grid, THREADS>>>(
        wfeat, bfeat, ft_w, stm, ft_b, l1_w, l1_b, l2_w, l2_b, out);
}